// round 16
// baseline (speedup 1.0000x reference)
#include <cuda_runtime.h>
#include <cuda_bf16.h>
#include <math.h>
#include <cstdint>

// Problem constants
#define TT   4096
#define HH   1024
#define FF   2048
#define NE   8
#define GHD  1024
#define CROWS 8192

// ------------------------- device scratch -----------------------------------
__device__ __nv_bfloat16 g_xs  [(size_t)TT * 2 * HH];      // X bf16 split
__device__ __nv_bfloat16 g_gw1s[(size_t)GHD * 2 * HH];     // gw1^T bf16 split
__device__ __nv_bfloat16 g_w1s [(size_t)NE * FF * 2 * HH]; // w1^T bf16 split
__device__ __nv_bfloat16 g_w3s [(size_t)NE * FF * 2 * HH];
__device__ __nv_bfloat16 g_w2s [(size_t)NE * HH * 2 * FF];
__device__ __nv_bfloat16 g_hs  [(size_t)CROWS * 2 * FF];   // h bf16 split
__device__ float g_y  [(size_t)CROWS * HH];                // down output, compact
__device__ float g_act[(size_t)TT * GHD];
__device__ int   g_idx[NE * TT];
__device__ float g_wt [NE * TT];
__device__ int   g_slot[2 * TT];
__device__ int   g_cnt[NE];
__device__ int   g_off[NE];

// ------------------------- PTX helpers --------------------------------------
__device__ __forceinline__ uint32_t smem_u32(const void* p) {
    uint32_t a;
    asm("{ .reg .u64 t; cvta.to.shared.u64 t, %1; cvt.u32.u64 %0, t; }" : "=r"(a) : "l"(p));
    return a;
}
#define CP16(dst, src) \
    asm volatile("cp.async.cg.shared.global [%0], [%1], 16;" :: "r"(dst), "l"(src))
#define CP_COMMIT() asm volatile("cp.async.commit_group;" ::: "memory")
#define CP_WAIT(n)  asm volatile("cp.async.wait_group %0;" :: "n"(n) : "memory")

#define LDSM4(r0, r1, r2, r3, addr) \
    asm volatile("ldmatrix.sync.aligned.m8n8.x4.shared.b16 {%0,%1,%2,%3}, [%4];" \
        : "=r"(r0), "=r"(r1), "=r"(r2), "=r"(r3) : "r"(addr))

#define MMA16816(d, a, b) \
    asm volatile("mma.sync.aligned.m16n8k16.row.col.f32.bf16.bf16.f32 " \
        "{%0,%1,%2,%3}, {%4,%5,%6,%7}, {%8,%9}, {%0,%1,%2,%3};" \
        : "+f"((d)[0]), "+f"((d)[1]), "+f"((d)[2]), "+f"((d)[3]) \
        : "r"((a)[0]), "r"((a)[1]), "r"((a)[2]), "r"((a)[3]), "r"((b)[0]), "r"((b)[1]))

__device__ __forceinline__ void bsplit(float v, __nv_bfloat16& h, __nv_bfloat16& l) {
    h = __float2bfloat16_rn(v);
    l = __float2bfloat16_rn(v - __bfloat162float(h));
}

// ------------------------- small kernels ------------------------------------
__global__ void k_reset_cnt() { if (threadIdx.x < NE) g_cnt[threadIdx.x] = 0; }

__global__ void k_splitX(const float* __restrict__ X) {
    int i = blockIdx.x * blockDim.x + threadIdx.x;
    if (i >= TT * HH) return;
    int t = i >> 10, k = i & 1023;
    __nv_bfloat16 h, l; bsplit(X[i], h, l);
    __nv_bfloat16* r = g_xs + (size_t)t * 2 * HH;
    r[k] = h; r[HH + k] = l;
}

__global__ void k_trsplit(const float* __restrict__ in, __nv_bfloat16* __restrict__ out,
                          int R, int C) {
    __shared__ float t[64][33];
    size_t ioff = (size_t)blockIdx.z * R * C;
    size_t ooff = (size_t)blockIdx.z * C * 2 * R;
    int c0 = blockIdx.x * 32, r0 = blockIdx.y * 64;
    int tx = threadIdx.x, ty = threadIdx.y;
#pragma unroll
    for (int i = ty; i < 64; i += 8)
        t[i][tx] = in[ioff + (size_t)(r0 + i) * C + c0 + tx];
    __syncthreads();
    int tid = ty * 32 + tx;
    int cidx = tid >> 3, k0 = (tid & 7) * 8;
    uint32_t H[4], L[4];
#pragma unroll
    for (int j = 0; j < 4; j++) {
        float v0 = t[k0 + 2 * j + 0][cidx];
        float v1 = t[k0 + 2 * j + 1][cidx];
        __nv_bfloat16 h0, l0, h1, l1;
        bsplit(v0, h0, l0); bsplit(v1, h1, l1);
        __nv_bfloat162 hp; hp.x = h0; hp.y = h1;
        __nv_bfloat162 lp; lp.x = l0; lp.y = l1;
        H[j] = *(uint32_t*)&hp; L[j] = *(uint32_t*)&lp;
    }
    __nv_bfloat16* orow = out + ooff + (size_t)(c0 + cidx) * 2 * R;
    int k = r0 + k0;
    *(uint4*)&orow[k]     = make_uint4(H[0], H[1], H[2], H[3]);
    *(uint4*)&orow[R + k] = make_uint4(L[0], L[1], L[2], L[3]);
}

__global__ void k_route(const float* __restrict__ W2, const float* __restrict__ b2,
                        float* __restrict__ logits_out) {
    int gt = blockIdx.x * (blockDim.x >> 5) + (threadIdx.x >> 5);
    int lane = threadIdx.x & 31;
    if (gt >= TT) return;
    const float* g = g_act + (size_t)gt * GHD;
    float s[NE] = {};
    for (int k = lane; k < GHD; k += 32) {
        float gv = g[k];
        const float* wr = W2 + (size_t)k * NE;
#pragma unroll
        for (int e = 0; e < NE; e++) s[e] = fmaf(gv, wr[e], s[e]);
    }
#pragma unroll
    for (int o = 16; o; o >>= 1)
#pragma unroll
        for (int e = 0; e < NE; e++) s[e] += __shfl_down_sync(0xffffffffu, s[e], o);
    if (lane == 0) {
        float lg[NE]; float mx = -1e30f;
#pragma unroll
        for (int e = 0; e < NE; e++) {
            lg[e] = s[e] + b2[e];
            logits_out[(size_t)gt * NE + e] = lg[e];
            mx = fmaxf(mx, lg[e]);
        }
        float ex[NE], S = 0.0f;
#pragma unroll
        for (int e = 0; e < NE; e++) { ex[e] = expf(lg[e] - mx); S += ex[e]; }
        float p[NE];
#pragma unroll
        for (int e = 0; e < NE; e++) p[e] = ex[e] / S;
        int i0 = 0;
#pragma unroll
        for (int e = 1; e < NE; e++) if (p[e] > p[i0]) i0 = e;
        int i1 = -1;
#pragma unroll
        for (int e = 0; e < NE; e++) {
            if (e == i0) continue;
            if (i1 < 0 || p[e] > p[i1]) i1 = e;
        }
        float tw = p[i0] + p[i1];
        int q0 = atomicAdd(&g_cnt[i0], 1);
        g_idx[i0 * TT + q0] = gt;  g_wt[i0 * TT + q0] = p[i0] / tw;
        g_slot[2 * gt + 0] = i0 * TT + q0;
        int q1 = atomicAdd(&g_cnt[i1], 1);
        g_idx[i1 * TT + q1] = gt;  g_wt[i1 * TT + q1] = p[i1] / tw;
        g_slot[2 * gt + 1] = i1 * TT + q1;
    }
}

__global__ void k_off_k() {
    if (threadIdx.x == 0) {
        int a = 0;
#pragma unroll
        for (int e = 0; e < NE; e++) { g_off[e] = a; a += g_cnt[e]; }
    }
}

__global__ void k_combine(float* __restrict__ out) {
    int i = blockIdx.x * 256 + threadIdx.x;
    if (i >= TT * (HH / 4)) return;
    int t = i / (HH / 4), n4 = (i % (HH / 4)) * 4;
    int s0 = g_slot[2 * t], s1 = g_slot[2 * t + 1];
    float w0 = g_wt[s0], w1 = g_wt[s1];
    int r0 = g_off[s0 >> 12] + (s0 & 4095);
    int r1 = g_off[s1 >> 12] + (s1 & 4095);
    float4 a = *(float4*)&g_y[(size_t)r0 * HH + n4];
    float4 b = *(float4*)&g_y[(size_t)r1 * HH + n4];
    float4 o;
    o.x = w0 * a.x + w1 * b.x; o.y = w0 * a.y + w1 * b.y;
    o.z = w0 * a.z + w1 * b.z; o.w = w0 * a.w + w1 * b.w;
    *(float4*)&out[(size_t)t * HH + n4] = o;
}

// ------------- bf16 split GEMM, CTA 128 x 256 (validated R15 skeleton) -------
// MODE 0: gate  (A=g_xs, B=gw1s, out=g_act bias+ELU, K=HH, N-tile covers GHD)
// MODE 1: up    (A=g_xs gathered, B=interleaved w1/w3 32-row blocks, K=HH;
//                epilogue relu(u1)*u3 -> g_hs split; n-tile = 128 features)
// MODE 2: down  (A=g_hs compact, B=w2s, out=g_y compact rows, K=FF)
// 512 thr, 16 warps (4m x 4n), warp tile 32(M) x 64(N). Stage 48KB x 3.
template <int MODE>
__global__ void __launch_bounds__(512)
k_gemm(const __nv_bfloat16* __restrict__ Ab, const __nv_bfloat16* __restrict__ Bb,
       const __nv_bfloat16* __restrict__ Bb2,
       int K, float* __restrict__ outp, const float* __restrict__ bias) {
    const int e = blockIdx.z;
    const int m0 = blockIdx.y * 128;
    int cnt, hoff = 0;
    if (MODE == 0) cnt = TT;
    else {
        cnt = g_cnt[e];
        if (m0 >= cnt) return;
        hoff = g_off[e];
    }
    // n0: combined-tile origin. MODE 1: feature tile of 128 (combined width 256).
    const int n0 = blockIdx.x * (MODE == 1 ? 128 : 256);
    const int bRows = (MODE == 2) ? HH : GHD;   // unused for MODE 1
    const __nv_bfloat16* Bex =
        (MODE == 2) ? Bb + (size_t)e * bRows * 2 * K : Bb;

    extern __shared__ char sm[];
    const uint32_t sbase = smem_u32(sm);
    const int tid = threadIdx.x;
    const int lane = tid & 31, wid = tid >> 5;
    const int wm = wid & 3, wn = wid >> 2;

    // A loader: 128 rows x 4 chunks; 1 CP16 per zone per thread
    const int lr = tid >> 2, cp = tid & 3;
    const __nv_bfloat16* arow;
    if (MODE == 0) {
        arow = Ab + (size_t)(m0 + lr) * 2 * K;
    } else if (MODE == 1) {
        int slot = m0 + lr; if (slot >= cnt) slot = cnt - 1;
        arow = Ab + (size_t)g_idx[e * TT + slot] * 2 * K;
    } else {
        int rr = hoff + m0 + lr; if (rr > CROWS - 1) rr = CROWS - 1;
        arow = Ab + (size_t)rr * 2 * K;
    }
    const uint32_t dOffA = lr * 64 + ((cp ^ ((lr >> 1) & 3)) << 4);
    // B loader: 256 combined rows x 4 chunks; 2 CP16 per zone per thread
    const int rb = tid >> 1, cb0 = (tid & 1) * 2;
    const __nv_bfloat16* brow;
    if (MODE == 1) {
        // combined row rb: feature = n0 + (rb>>6)*32 + (rb&31); matrix = (rb>>5)&1
        int feat = n0 + ((rb >> 6) << 5) + (rb & 31);
        const __nv_bfloat16* base = ((rb >> 5) & 1) ? Bb2 : Bb;
        brow = base + (size_t)e * FF * 2 * K + (size_t)feat * 2 * K;
    } else {
        brow = Bex + (size_t)(n0 + rb) * 2 * K;
    }
    const int selB_st = (rb >> 1) & 3;
    const uint32_t dOffB0 = rb * 64 + (((cb0 + 0) ^ selB_st) << 4);
    const uint32_t dOffB1 = rb * 64 + (((cb0 + 1) ^ selB_st) << 4);

    const int t8 = lane >> 3, i7 = lane & 7;
    const int rowA = wm * 32 + (t8 & 1) * 8 + i7;
    const int rowB = wn * 64 + (t8 >> 1) * 8 + i7;
    const int selA = (rowA >> 1) & 3, cbA = t8 >> 1;
    const int cbB = t8 & 1;

    float acc[2][8][4] = {};
    const int KT = K >> 5;
#pragma unroll
    for (int s = 0; s < 2; s++) {
        uint32_t st = sbase + s * 49152;
        int colA = s * 32 + cp * 8;
        int colB0 = s * 32 + (cb0 + 0) * 8, colB1 = s * 32 + (cb0 + 1) * 8;
        CP16(st +         dOffA, arow + colA);
        CP16(st +  8192 + dOffA, arow + K + colA);
        CP16(st + 16384 + dOffB0, brow + colB0);
        CP16(st + 16384 + dOffB1, brow + colB1);
        CP16(st + 32768 + dOffB0, brow + K + colB0);
        CP16(st + 32768 + dOffB1, brow + K + colB1);
        CP_COMMIT();
    }

    for (int kt = 0; kt < KT; kt++) {
        CP_WAIT(1);
        __syncthreads();
        uint32_t st = sbase + (kt % 3) * 49152;
#pragma unroll
        for (int ks = 0; ks < 2; ks++) {
            uint32_t Ah[2][4], Al[2][4];
#pragma unroll
            for (int f = 0; f < 2; f++) {
                uint32_t aoff = (rowA + f * 16) * 64 + (((ks * 2 + cbA) ^ selA) << 4);
                LDSM4(Ah[f][0], Ah[f][1], Ah[f][2], Ah[f][3], st + aoff);
                LDSM4(Al[f][0], Al[f][1], Al[f][2], Al[f][3], st + 8192 + aoff);
            }
#pragma unroll
            for (int gh = 0; gh < 2; gh++) {
                uint32_t Bh[4][2], Bl[4][2];
#pragma unroll
                for (int p = 0; p < 2; p++) {
                    int prow = rowB + gh * 32 + p * 16;
                    int psel = (prow >> 1) & 3;
                    uint32_t boff = prow * 64 + (((ks * 2 + cbB) ^ psel) << 4);
                    LDSM4(Bh[2 * p][0], Bh[2 * p][1], Bh[2 * p + 1][0], Bh[2 * p + 1][1],
                          st + 16384 + boff);
                    LDSM4(Bl[2 * p][0], Bl[2 * p][1], Bl[2 * p + 1][0], Bl[2 * p + 1][1],
                          st + 32768 + boff);
                }
#pragma unroll
                for (int f = 0; f < 2; f++)
#pragma unroll
                    for (int g = 0; g < 4; g++) {
                        MMA16816(acc[f][gh * 4 + g], Ah[f], Bh[g]);
                        MMA16816(acc[f][gh * 4 + g], Ah[f], Bl[g]);
                        MMA16816(acc[f][gh * 4 + g], Al[f], Bh[g]);
                    }
            }
        }
        int nk = kt + 2;
        if (nk < KT) {
            uint32_t stw = sbase + (nk % 3) * 49152;
            int colA = nk * 32 + cp * 8;
            int colB0 = nk * 32 + (cb0 + 0) * 8, colB1 = nk * 32 + (cb0 + 1) * 8;
            CP16(stw +         dOffA, arow + colA);
            CP16(stw +  8192 + dOffA, arow + K + colA);
            CP16(stw + 16384 + dOffB0, brow + colB0);
            CP16(stw + 16384 + dOffB1, brow + colB1);
            CP16(stw + 32768 + dOffB0, brow + K + colB0);
            CP16(stw + 32768 + dOffB1, brow + K + colB1);
        }
        CP_COMMIT();
    }

    const int rg = lane >> 2, cq = (lane & 3) * 2;
#pragma unroll
    for (int f = 0; f < 2; f++) {
#pragma unroll
        for (int half = 0; half < 2; half++) {
            int mrel = wm * 32 + f * 16 + rg + half * 8;
            if (MODE == 1) {
                int srow = m0 + mrel;
                if (srow < cnt) {
                    __nv_bfloat16* rowp = g_hs + (size_t)(hoff + srow) * 2 * FF;
#pragma unroll
                    for (int g = 0; g < 4; g++) {
                        int n = n0 + wn * 32 + g * 8 + cq;
                        float u1a = acc[f][g][half * 2 + 0];
                        float u1b = acc[f][g][half * 2 + 1];
                        float u3a = acc[f][4 + g][half * 2 + 0];
                        float u3b = acc[f][4 + g][half * 2 + 1];
                        float h0 = fmaxf(u1a, 0.f) * u3a;
                        float h1 = fmaxf(u1b, 0.f) * u3b;
                        __nv_bfloat16 hh0, hl0, hh1, hl1;
                        bsplit(h0, hh0, hl0); bsplit(h1, hh1, hl1);
                        __nv_bfloat162 hi; hi.x = hh0; hi.y = hh1;
                        __nv_bfloat162 lo; lo.x = hl0; lo.y = hl1;
                        *(__nv_bfloat162*)&rowp[n]      = hi;
                        *(__nv_bfloat162*)&rowp[FF + n] = lo;
                    }
                }
            } else {
#pragma unroll
                for (int g = 0; g < 8; g++) {
                    float v0 = acc[f][g][half * 2 + 0];
                    float v1 = acc[f][g][half * 2 + 1];
                    int n = n0 + wn * 64 + g * 8 + cq;
                    if (MODE == 0) {
                        int m = m0 + mrel;
                        float a0 = v0 + bias[n], a1 = v1 + bias[n + 1];
                        a0 = a0 > 0.f ? a0 : expm1f(a0);
                        a1 = a1 > 0.f ? a1 : expm1f(a1);
                        *(float2*)&g_act[(size_t)m * GHD + n] = make_float2(a0, a1);
                    } else {
                        int slot = m0 + mrel;
                        if (slot < cnt)
                            *(float2*)&g_y[(size_t)(hoff + slot) * HH + n] = make_float2(v0, v1);
                    }
                }
            }
        }
    }
}

// ------------------------- launch -------------------------------------------
extern "C" void kernel_launch(void* const* d_in, const int* in_sizes, int n_in,
                              void* d_out, int out_size) {
    const float* x   = (const float*)d_in[0];
    const float* gw1 = (const float*)d_in[1];
    const float* gb1 = (const float*)d_in[2];
    const float* gw2 = (const float*)d_in[3];
    const float* gb2 = (const float*)d_in[4];
    const float* w1  = (const float*)d_in[5];
    const float* w3  = (const float*)d_in[6];
    const float* w2  = (const float*)d_in[7];
    float* out    = (float*)d_out;
    float* logits = out + (size_t)TT * HH;

    __nv_bfloat16 *d_xs, *d_gw1s, *d_w1s, *d_w3s, *d_w2s, *d_hs;
    cudaGetSymbolAddress((void**)&d_xs,   g_xs);
    cudaGetSymbolAddress((void**)&d_gw1s, g_gw1s);
    cudaGetSymbolAddress((void**)&d_w1s,  g_w1s);
    cudaGetSymbolAddress((void**)&d_w3s,  g_w3s);
    cudaGetSymbolAddress((void**)&d_w2s,  g_w2s);
    cudaGetSymbolAddress((void**)&d_hs,   g_hs);
    float *d_act, *d_y;
    cudaGetSymbolAddress((void**)&d_act, g_act);
    cudaGetSymbolAddress((void**)&d_y,   g_y);

    const int SMEMG = 3 * 49152;    // 144KB
    cudaFuncSetAttribute(k_gemm<0>, cudaFuncAttributeMaxDynamicSharedMemorySize, SMEMG);
    cudaFuncSetAttribute(k_gemm<1>, cudaFuncAttributeMaxDynamicSharedMemorySize, SMEMG);
    cudaFuncSetAttribute(k_gemm<2>, cudaFuncAttributeMaxDynamicSharedMemorySize, SMEMG);

    k_reset_cnt<<<1, 32>>>();
    k_splitX<<<(TT * HH + 255) / 256, 256>>>(x);
    k_trsplit<<<dim3(GHD / 32, HH / 64, 1),  dim3(32, 8)>>>(gw1, d_gw1s, HH, GHD);
    k_trsplit<<<dim3(FF / 32,  HH / 64, NE), dim3(32, 8)>>>(w1,  d_w1s,  HH, FF);
    k_trsplit<<<dim3(FF / 32,  HH / 64, NE), dim3(32, 8)>>>(w3,  d_w3s,  HH, FF);
    k_trsplit<<<dim3(HH / 32,  FF / 64, NE), dim3(32, 8)>>>(w2,  d_w2s,  FF, HH);

    // gate: X @ gw1^T -> g_act (bias+ELU)
    k_gemm<0><<<dim3(GHD / 256, TT / 128, 1), 512, SMEMG>>>(d_xs, d_gw1s, nullptr, HH, d_act, gb1);
    k_route<<<TT / 8, 256>>>(gw2, gb2, logits);
    k_off_k<<<1, 32>>>();
    // fused up: gathered X @ (w1,w3) interleaved -> g_hs split
    k_gemm<1><<<dim3(FF / 128, TT / 128, NE), 512, SMEMG>>>(d_xs, d_w1s, d_w3s, HH, nullptr, nullptr);
    // down: h @ w2^T -> g_y compact
    k_gemm<2><<<dim3(HH / 256, TT / 128, NE), 512, SMEMG>>>(d_hs, d_w2s, nullptr, FF, d_y, nullptr);
    k_combine<<<(TT * (HH / 4) + 255) / 256, 256>>>(out);
}

// round 17
// speedup vs baseline: 1.2128x; 1.2128x over previous
#include <cuda_runtime.h>
#include <cuda_bf16.h>
#include <math.h>
#include <cstdint>

// Problem constants
#define TT   4096
#define HH   1024
#define FF   2048
#define NE   8
#define GHD  1024
#define CROWS 8192
#define QM   32512.0f    // 127*256: 15-bit quant full-scale

// ------------------------- device scratch -----------------------------------
__device__ __nv_bfloat16 g_xs  [(size_t)TT * 2 * HH];      // X bf16 split (gate)
__device__ __nv_bfloat16 g_gw1s[(size_t)GHD * 2 * HH];     // gw1^T bf16 split
__device__ __nv_bfloat16 g_w2s [(size_t)NE * HH * 2 * FF]; // w2^T bf16 split
__device__ __nv_bfloat16 g_hs  [(size_t)CROWS * 2 * FF];   // h bf16 split
__device__ int8_t g_xq [(size_t)TT * 2 * HH];              // X int8 [ah|al]
__device__ int8_t g_w1q[(size_t)NE * FF * 2 * HH];         // w1^T int8 [N,[ah|al]]
__device__ int8_t g_w3q[(size_t)NE * FF * 2 * HH];
__device__ float g_sx [TT];
__device__ float g_sw1[NE * FF];
__device__ float g_sw3[NE * FF];
__device__ float g_y  [(size_t)CROWS * HH];                // down output, compact
__device__ float g_act[(size_t)TT * GHD];
__device__ int   g_idx[NE * TT];
__device__ float g_wt [NE * TT];
__device__ int   g_slot[2 * TT];
__device__ int   g_cnt[NE];
__device__ int   g_off[NE];

// ------------------------- PTX helpers --------------------------------------
__device__ __forceinline__ uint32_t smem_u32(const void* p) {
    uint32_t a;
    asm("{ .reg .u64 t; cvta.to.shared.u64 t, %1; cvt.u32.u64 %0, t; }" : "=r"(a) : "l"(p));
    return a;
}
#define CP16(dst, src) \
    asm volatile("cp.async.cg.shared.global [%0], [%1], 16;" :: "r"(dst), "l"(src))
#define CP_COMMIT() asm volatile("cp.async.commit_group;" ::: "memory")
#define CP_WAIT(n)  asm volatile("cp.async.wait_group %0;" :: "n"(n) : "memory")

#define LDSM4(r0, r1, r2, r3, addr) \
    asm volatile("ldmatrix.sync.aligned.m8n8.x4.shared.b16 {%0,%1,%2,%3}, [%4];" \
        : "=r"(r0), "=r"(r1), "=r"(r2), "=r"(r3) : "r"(addr))

#define MMA16816(d, a, b) \
    asm volatile("mma.sync.aligned.m16n8k16.row.col.f32.bf16.bf16.f32 " \
        "{%0,%1,%2,%3}, {%4,%5,%6,%7}, {%8,%9}, {%0,%1,%2,%3};" \
        : "+f"((d)[0]), "+f"((d)[1]), "+f"((d)[2]), "+f"((d)[3]) \
        : "r"((a)[0]), "r"((a)[1]), "r"((a)[2]), "r"((a)[3]), "r"((b)[0]), "r"((b)[1]))

#define MMAS8(d, a, b) \
    asm volatile("mma.sync.aligned.m16n8k32.row.col.s32.s8.s8.s32 " \
        "{%0,%1,%2,%3}, {%4,%5,%6,%7}, {%8,%9}, {%0,%1,%2,%3};" \
        : "+r"((d)[0]), "+r"((d)[1]), "+r"((d)[2]), "+r"((d)[3]) \
        : "r"((a)[0]), "r"((a)[1]), "r"((a)[2]), "r"((a)[3]), "r"((b)[0]), "r"((b)[1]))

__device__ __forceinline__ void bsplit(float v, __nv_bfloat16& h, __nv_bfloat16& l) {
    h = __float2bfloat16_rn(v);
    l = __float2bfloat16_rn(v - __bfloat162float(h));
}

// ------------------------- small kernels ------------------------------------
__global__ void k_reset_cnt() { if (threadIdx.x < NE) g_cnt[threadIdx.x] = 0; }

// merged: X fp32 -> bf16 split (g_xs) + 15-bit int8 split (g_xq) + scale
__global__ void k_splitqx(const float* __restrict__ X) {
    int t = blockIdx.x, tid = threadIdx.x;
    __shared__ float red[128];
    const float* xr = X + (size_t)t * HH;
    float v[8], mx = 0.f;
#pragma unroll
    for (int j = 0; j < 8; j++) { v[j] = xr[tid + 128 * j]; mx = fmaxf(mx, fabsf(v[j])); }
    red[tid] = mx; __syncthreads();
    for (int s = 64; s > 0; s >>= 1) {
        if (tid < s) red[tid] = fmaxf(red[tid], red[tid + s]);
        __syncthreads();
    }
    float m = fmaxf(red[0], 1e-20f);
    if (tid == 0) g_sx[t] = m / QM;
    float qmul = QM / m;
    int8_t* r = g_xq + (size_t)t * 2 * HH;
    __nv_bfloat16* rs = g_xs + (size_t)t * 2 * HH;
#pragma unroll
    for (int j = 0; j < 8; j++) {
        int k = tid + 128 * j;
        int q = __float2int_rn(v[j] * qmul);
        int ah = (q + 128) >> 8, al = q - (ah << 8);
        r[k] = (int8_t)ah;
        r[HH + k] = (int8_t)al;
        __nv_bfloat16 h, l; bsplit(v[j], h, l);
        rs[k] = h; rs[HH + k] = l;
    }
}

// both w1 and w3 per-feature absmax in one launch
__global__ void k_wmax2(const float* __restrict__ in1, const float* __restrict__ in3,
                        float* __restrict__ sd1, float* __restrict__ sd3, int R, int C) {
    int e = blockIdx.z, n = blockIdx.x * 256 + threadIdx.x;
    const float* p1 = in1 + (size_t)e * R * C + n;
    const float* p3 = in3 + (size_t)e * R * C + n;
    float m1 = 0.f, m3 = 0.f;
    for (int r = 0; r < R; r++) {
        m1 = fmaxf(m1, fabsf(p1[(size_t)r * C]));
        m3 = fmaxf(m3, fabsf(p3[(size_t)r * C]));
    }
    sd1[e * C + n] = fmaxf(m1, 1e-20f) / QM;
    sd3[e * C + n] = fmaxf(m3, 1e-20f) / QM;
}

__global__ void k_trquant(const float* __restrict__ in, int8_t* __restrict__ out,
                          const float* __restrict__ sd, int R, int C) {
    __shared__ float t[64][33];
    __shared__ float qm[32];
    int e = blockIdx.z;
    size_t ioff = (size_t)e * R * C, ooff = (size_t)e * C * 2 * R;
    int c0 = blockIdx.x * 32, r0 = blockIdx.y * 64;
    int tx = threadIdx.x, ty = threadIdx.y;
    if (ty == 0) qm[tx] = 1.0f / sd[e * C + c0 + tx];
#pragma unroll
    for (int i = ty; i < 64; i += 8)
        t[i][tx] = in[ioff + (size_t)(r0 + i) * C + c0 + tx];
    __syncthreads();
    int tid = ty * 32 + tx;
    int cidx = tid >> 3, k0 = (tid & 7) * 8;
    float s = qm[cidx];
    uint8_t ahb[8], alb[8];
#pragma unroll
    for (int j = 0; j < 8; j++) {
        int q = __float2int_rn(t[k0 + j][cidx] * s);
        int ah = (q + 128) >> 8, al = q - (ah << 8);
        ahb[j] = (uint8_t)(int8_t)ah; alb[j] = (uint8_t)(int8_t)al;
    }
    int8_t* orow = out + ooff + (size_t)(c0 + cidx) * 2 * R;
    int k = r0 + k0;
    *(uint2*)&orow[k]     = *(uint2*)ahb;
    *(uint2*)&orow[R + k] = *(uint2*)alb;
}

__global__ void k_trsplit(const float* __restrict__ in, __nv_bfloat16* __restrict__ out,
                          int R, int C) {
    __shared__ float t[64][33];
    size_t ioff = (size_t)blockIdx.z * R * C;
    size_t ooff = (size_t)blockIdx.z * C * 2 * R;
    int c0 = blockIdx.x * 32, r0 = blockIdx.y * 64;
    int tx = threadIdx.x, ty = threadIdx.y;
#pragma unroll
    for (int i = ty; i < 64; i += 8)
        t[i][tx] = in[ioff + (size_t)(r0 + i) * C + c0 + tx];
    __syncthreads();
    int tid = ty * 32 + tx;
    int cidx = tid >> 3, k0 = (tid & 7) * 8;
    uint32_t H[4], L[4];
#pragma unroll
    for (int j = 0; j < 4; j++) {
        float v0 = t[k0 + 2 * j + 0][cidx];
        float v1 = t[k0 + 2 * j + 1][cidx];
        __nv_bfloat16 h0, l0, h1, l1;
        bsplit(v0, h0, l0); bsplit(v1, h1, l1);
        __nv_bfloat162 hp; hp.x = h0; hp.y = h1;
        __nv_bfloat162 lp; lp.x = l0; lp.y = l1;
        H[j] = *(uint32_t*)&hp; L[j] = *(uint32_t*)&lp;
    }
    __nv_bfloat16* orow = out + ooff + (size_t)(c0 + cidx) * 2 * R;
    int k = r0 + k0;
    *(uint4*)&orow[k]     = make_uint4(H[0], H[1], H[2], H[3]);
    *(uint4*)&orow[R + k] = make_uint4(L[0], L[1], L[2], L[3]);
}

__global__ void k_route(const float* __restrict__ W2, const float* __restrict__ b2,
                        float* __restrict__ logits_out) {
    int gt = blockIdx.x * (blockDim.x >> 5) + (threadIdx.x >> 5);
    int lane = threadIdx.x & 31;
    if (gt >= TT) return;
    const float* g = g_act + (size_t)gt * GHD;
    float s[NE] = {};
    for (int k = lane; k < GHD; k += 32) {
        float gv = g[k];
        const float* wr = W2 + (size_t)k * NE;
#pragma unroll
        for (int e = 0; e < NE; e++) s[e] = fmaf(gv, wr[e], s[e]);
    }
#pragma unroll
    for (int o = 16; o; o >>= 1)
#pragma unroll
        for (int e = 0; e < NE; e++) s[e] += __shfl_down_sync(0xffffffffu, s[e], o);
    if (lane == 0) {
        float lg[NE]; float mx = -1e30f;
#pragma unroll
        for (int e = 0; e < NE; e++) {
            lg[e] = s[e] + b2[e];
            logits_out[(size_t)gt * NE + e] = lg[e];
            mx = fmaxf(mx, lg[e]);
        }
        float ex[NE], S = 0.0f;
#pragma unroll
        for (int e = 0; e < NE; e++) { ex[e] = expf(lg[e] - mx); S += ex[e]; }
        float p[NE];
#pragma unroll
        for (int e = 0; e < NE; e++) p[e] = ex[e] / S;
        int i0 = 0;
#pragma unroll
        for (int e = 1; e < NE; e++) if (p[e] > p[i0]) i0 = e;
        int i1 = -1;
#pragma unroll
        for (int e = 0; e < NE; e++) {
            if (e == i0) continue;
            if (i1 < 0 || p[e] > p[i1]) i1 = e;
        }
        float tw = p[i0] + p[i1];
        int q0 = atomicAdd(&g_cnt[i0], 1);
        g_idx[i0 * TT + q0] = gt;  g_wt[i0 * TT + q0] = p[i0] / tw;
        g_slot[2 * gt + 0] = i0 * TT + q0;
        int q1 = atomicAdd(&g_cnt[i1], 1);
        g_idx[i1 * TT + q1] = gt;  g_wt[i1 * TT + q1] = p[i1] / tw;
        g_slot[2 * gt + 1] = i1 * TT + q1;
    }
}

__global__ void k_off_k() {
    if (threadIdx.x == 0) {
        int a = 0;
#pragma unroll
        for (int e = 0; e < NE; e++) { g_off[e] = a; a += g_cnt[e]; }
    }
}

__global__ void k_combine(float* __restrict__ out) {
    int i = blockIdx.x * 256 + threadIdx.x;
    if (i >= TT * (HH / 4)) return;
    int t = i / (HH / 4), n4 = (i % (HH / 4)) * 4;
    int s0 = g_slot[2 * t], s1 = g_slot[2 * t + 1];
    float w0 = g_wt[s0], w1 = g_wt[s1];
    int r0 = g_off[s0 >> 12] + (s0 & 4095);
    int r1 = g_off[s1 >> 12] + (s1 & 4095);
    float4 a = *(float4*)&g_y[(size_t)r0 * HH + n4];
    float4 b = *(float4*)&g_y[(size_t)r1 * HH + n4];
    float4 o;
    o.x = w0 * a.x + w1 * b.x; o.y = w0 * a.y + w1 * b.y;
    o.z = w0 * a.z + w1 * b.z; o.w = w0 * a.w + w1 * b.w;
    *(float4*)&out[(size_t)t * HH + n4] = o;
}

// ------------- bf16 split GEMM (gate / down), CTA 128 x 256 ------------------
template <int MODE>
__global__ void __launch_bounds__(512)
k_gemm(const __nv_bfloat16* __restrict__ Ab, const __nv_bfloat16* __restrict__ Bb,
       int K, float* __restrict__ outp, const float* __restrict__ bias) {
    const int e = blockIdx.z;
    const int m0 = blockIdx.y * 128, n0 = blockIdx.x * 256;
    int cnt, hoff = 0;
    if (MODE == 0) cnt = TT;
    else {
        cnt = g_cnt[e];
        if (m0 >= cnt) return;
        hoff = g_off[e];
    }
    const int bRows = (MODE == 2) ? HH : GHD;
    const __nv_bfloat16* Bex = Bb + (MODE == 0 ? (size_t)0 : (size_t)e * bRows * 2 * K);

    extern __shared__ char sm[];
    const uint32_t sbase = smem_u32(sm);
    const int tid = threadIdx.x;
    const int lane = tid & 31, wid = tid >> 5;
    const int wm = wid & 3, wn = wid >> 2;

    const int lr = tid >> 2, cp = tid & 3;
    const __nv_bfloat16* arow;
    if (MODE == 0) {
        arow = Ab + (size_t)(m0 + lr) * 2 * K;
    } else {
        int rr = hoff + m0 + lr; if (rr > CROWS - 1) rr = CROWS - 1;
        arow = Ab + (size_t)rr * 2 * K;
    }
    const uint32_t dOffA = lr * 64 + ((cp ^ ((lr >> 1) & 3)) << 4);
    const int rb = tid >> 1, cb0 = (tid & 1) * 2;
    const __nv_bfloat16* brow = Bex + (size_t)(n0 + rb) * 2 * K;
    const int selB_st = (rb >> 1) & 3;
    const uint32_t dOffB0 = rb * 64 + (((cb0 + 0) ^ selB_st) << 4);
    const uint32_t dOffB1 = rb * 64 + (((cb0 + 1) ^ selB_st) << 4);

    const int t8 = lane >> 3, i7 = lane & 7;
    const int rowA = wm * 32 + (t8 & 1) * 8 + i7;
    const int rowB = wn * 64 + (t8 >> 1) * 8 + i7;
    const int selA = (rowA >> 1) & 3, cbA = t8 >> 1;
    const int cbB = t8 & 1;

    float acc[2][8][4] = {};
    const int KT = K >> 5;
#pragma unroll
    for (int s = 0; s < 2; s++) {
        uint32_t st = sbase + s * 49152;
        int colA = s * 32 + cp * 8;
        int colB0 = s * 32 + (cb0 + 0) * 8, colB1 = s * 32 + (cb0 + 1) * 8;
        CP16(st +         dOffA, arow + colA);
        CP16(st +  8192 + dOffA, arow + K + colA);
        CP16(st + 16384 + dOffB0, brow + colB0);
        CP16(st + 16384 + dOffB1, brow + colB1);
        CP16(st + 32768 + dOffB0, brow + K + colB0);
        CP16(st + 32768 + dOffB1, brow + K + colB1);
        CP_COMMIT();
    }

    for (int kt = 0; kt < KT; kt++) {
        CP_WAIT(1);
        __syncthreads();
        uint32_t st = sbase + (kt % 3) * 49152;
#pragma unroll
        for (int ks = 0; ks < 2; ks++) {
            uint32_t Ah[2][4], Al[2][4];
#pragma unroll
            for (int f = 0; f < 2; f++) {
                uint32_t aoff = (rowA + f * 16) * 64 + (((ks * 2 + cbA) ^ selA) << 4);
                LDSM4(Ah[f][0], Ah[f][1], Ah[f][2], Ah[f][3], st + aoff);
                LDSM4(Al[f][0], Al[f][1], Al[f][2], Al[f][3], st + 8192 + aoff);
            }
#pragma unroll
            for (int gh = 0; gh < 2; gh++) {
                uint32_t Bh[4][2], Bl[4][2];
#pragma unroll
                for (int p = 0; p < 2; p++) {
                    int prow = rowB + gh * 32 + p * 16;
                    int psel = (prow >> 1) & 3;
                    uint32_t boff = prow * 64 + (((ks * 2 + cbB) ^ psel) << 4);
                    LDSM4(Bh[2 * p][0], Bh[2 * p][1], Bh[2 * p + 1][0], Bh[2 * p + 1][1],
                          st + 16384 + boff);
                    LDSM4(Bl[2 * p][0], Bl[2 * p][1], Bl[2 * p + 1][0], Bl[2 * p + 1][1],
                          st + 32768 + boff);
                }
#pragma unroll
                for (int f = 0; f < 2; f++)
#pragma unroll
                    for (int g = 0; g < 4; g++) {
                        MMA16816(acc[f][gh * 4 + g], Ah[f], Bh[g]);
                        MMA16816(acc[f][gh * 4 + g], Ah[f], Bl[g]);
                        MMA16816(acc[f][gh * 4 + g], Al[f], Bh[g]);
                    }
            }
        }
        int nk = kt + 2;
        if (nk < KT) {
            uint32_t stw = sbase + (nk % 3) * 49152;
            int colA = nk * 32 + cp * 8;
            int colB0 = nk * 32 + (cb0 + 0) * 8, colB1 = nk * 32 + (cb0 + 1) * 8;
            CP16(stw +         dOffA, arow + colA);
            CP16(stw +  8192 + dOffA, arow + K + colA);
            CP16(stw + 16384 + dOffB0, brow + colB0);
            CP16(stw + 16384 + dOffB1, brow + colB1);
            CP16(stw + 32768 + dOffB0, brow + K + colB0);
            CP16(stw + 32768 + dOffB1, brow + K + colB1);
        }
        CP_COMMIT();
    }

    const int rg = lane >> 2, cq = (lane & 3) * 2;
#pragma unroll
    for (int f = 0; f < 2; f++) {
#pragma unroll
        for (int half = 0; half < 2; half++) {
            int mrel = wm * 32 + f * 16 + rg + half * 8;
#pragma unroll
            for (int g = 0; g < 8; g++) {
                float v0 = acc[f][g][half * 2 + 0];
                float v1 = acc[f][g][half * 2 + 1];
                int n = n0 + wn * 64 + g * 8 + cq;
                if (MODE == 0) {
                    int m = m0 + mrel;
                    float a0 = v0 + bias[n], a1 = v1 + bias[n + 1];
                    a0 = a0 > 0.f ? a0 : expm1f(a0);
                    a1 = a1 > 0.f ? a1 : expm1f(a1);
                    *(float2*)&g_act[(size_t)m * GHD + n] = make_float2(a0, a1);
                } else {
                    int slot = m0 + mrel;
                    if (slot < cnt)
                        *(float2*)&g_y[(size_t)(hoff + slot) * HH + n] = make_float2(v0, v1);
                }
            }
        }
    }
}

// ------------------- int8 fused up GEMM (R11/R15 config: 512 thr, N=64) ------
__global__ void __launch_bounds__(512)
k_upq() {
    const int e = blockIdx.z;
    const int cnt = g_cnt[e];
    const int m0 = blockIdx.y * 128;
    if (m0 >= cnt) return;
    const int n0 = blockIdx.x * 64;

    extern __shared__ char sm[];
    const uint32_t sbase = smem_u32(sm);
    const int tid = threadIdx.x;
    const int lane = tid & 31, wid = tid >> 5;
    const int wm = wid & 3, wn = wid >> 2;

    const int ra = tid >> 2, ca = tid & 3;
    int slotL = m0 + ra; if (slotL >= cnt) slotL = cnt - 1;
    const int8_t* arow = g_xq + (size_t)g_idx[e * TT + slotL] * 2 * HH;
    const uint32_t dOffA = ra * 64 + (((ca ^ ((ra >> 1) & 3))) << 4);
    const int rb = (tid & 255) >> 2, cbk = tid & 3, zb = tid >> 8;
    const int8_t* b1row = g_w1q + (size_t)e * FF * 2 * HH + (size_t)(n0 + rb) * 2 * HH;
    const int8_t* b3row = g_w3q + (size_t)e * FF * 2 * HH + (size_t)(n0 + rb) * 2 * HH;
    const uint32_t dOffB = zb * 4096 + rb * 64 + (((cbk ^ ((rb >> 1) & 3))) << 4);
    const int bsrcz = zb * HH;

    const int t8 = lane >> 3, i7 = lane & 7;
    const int rowA = wm * 32 + (t8 & 1) * 8 + i7;
    const int rowB = wn * 16 + (t8 >> 1) * 8 + i7;
    const int selA = (rowA >> 1) & 3, cbA = t8 >> 1;
    const int selB = (rowB >> 1) & 3, cbB = t8 & 1;

    int a1hh[2][2][4] = {}, a1x[2][2][4] = {};
    int a3hh[2][2][4] = {}, a3x[2][2][4] = {};

    const int KT = HH / 64;
#pragma unroll
    for (int s = 0; s < 2; s++) {
        uint32_t st = sbase + s * 32768;
        int k0 = s * 64;
        CP16(st +         dOffA, arow + k0 + ca * 16);
        CP16(st +  8192 + dOffA, arow + HH + k0 + ca * 16);
        CP16(st + 16384 + dOffB, b1row + bsrcz + k0 + cbk * 16);
        CP16(st + 24576 + dOffB, b3row + bsrcz + k0 + cbk * 16);
        CP_COMMIT();
    }

    for (int kt = 0; kt < KT; kt++) {
        CP_WAIT(1);
        __syncthreads();
        uint32_t st = sbase + (kt % 3) * 32768;
#pragma unroll
        for (int ks = 0; ks < 2; ks++) {
            uint32_t Ah[2][4], Al[2][4];
#pragma unroll
            for (int f = 0; f < 2; f++) {
                uint32_t aoff = (rowA + f * 16) * 64 + (((ks * 2 + cbA) ^ selA) << 4);
                LDSM4(Ah[f][0], Ah[f][1], Ah[f][2], Ah[f][3], st + aoff);
                LDSM4(Al[f][0], Al[f][1], Al[f][2], Al[f][3], st + 8192 + aoff);
            }
            uint32_t boff = rowB * 64 + (((ks * 2 + cbB) ^ selB) << 4);
            uint32_t B1h[2][2], B1l[2][2], B3h[2][2], B3l[2][2];
            LDSM4(B1h[0][0], B1h[0][1], B1h[1][0], B1h[1][1], st + 16384 + boff);
            LDSM4(B1l[0][0], B1l[0][1], B1l[1][0], B1l[1][1], st + 20480 + boff);
            LDSM4(B3h[0][0], B3h[0][1], B3h[1][0], B3h[1][1], st + 24576 + boff);
            LDSM4(B3l[0][0], B3l[0][1], B3l[1][0], B3l[1][1], st + 28672 + boff);
#pragma unroll
            for (int f = 0; f < 2; f++)
#pragma unroll
                for (int g = 0; g < 2; g++) {
                    MMAS8(a1hh[f][g], Ah[f], B1h[g]);
                    MMAS8(a1x [f][g], Ah[f], B1l[g]);
                    MMAS8(a1x [f][g], Al[f], B1h[g]);
                    MMAS8(a3hh[f][g], Ah[f], B3h[g]);
                    MMAS8(a3x [f][g], Ah[f], B3l[g]);
                    MMAS8(a3x [f][g], Al[f], B3h[g]);
                }
        }
        int nk = kt + 2;
        if (nk < KT) {
            uint32_t stw = sbase + (nk % 3) * 32768;
            int k0 = nk * 64;
            CP16(stw +         dOffA, arow + k0 + ca * 16);
            CP16(stw +  8192 + dOffA, arow + HH + k0 + ca * 16);
            CP16(stw + 16384 + dOffB, b1row + bsrcz + k0 + cbk * 16);
            CP16(stw + 24576 + dOffB, b3row + bsrcz + k0 + cbk * 16);
        }
        CP_COMMIT();
    }

    const int rg = lane >> 2, cq = (lane & 3) * 2;
    const int off = g_off[e];
#pragma unroll
    for (int f = 0; f < 2; f++) {
#pragma unroll
        for (int half = 0; half < 2; half++) {
            int mrel = wm * 32 + f * 16 + rg + half * 8;
            int srow = m0 + mrel;
            if (srow < cnt) {
                float sa = g_sx[g_idx[e * TT + srow]];
                __nv_bfloat16* rowp = g_hs + (size_t)(off + srow) * 2 * FF;
#pragma unroll
                for (int g = 0; g < 2; g++) {
                    int n = n0 + wn * 16 + g * 8 + cq;
                    float s1a = g_sw1[e * FF + n],     s1b = g_sw1[e * FF + n + 1];
                    float s3a = g_sw3[e * FF + n],     s3b = g_sw3[e * FF + n + 1];
                    float u1a = (65536.f * (float)a1hh[f][g][half * 2 + 0]
                               +   256.f * (float)a1x [f][g][half * 2 + 0]) * sa * s1a;
                    float u1b = (65536.f * (float)a1hh[f][g][half * 2 + 1]
                               +   256.f * (float)a1x [f][g][half * 2 + 1]) * sa * s1b;
                    float u3a = (65536.f * (float)a3hh[f][g][half * 2 + 0]
                               +   256.f * (float)a3x [f][g][half * 2 + 0]) * sa * s3a;
                    float u3b = (65536.f * (float)a3hh[f][g][half * 2 + 1]
                               +   256.f * (float)a3x [f][g][half * 2 + 1]) * sa * s3b;
                    float h0 = fmaxf(u1a, 0.f) * u3a;
                    float h1 = fmaxf(u1b, 0.f) * u3b;
                    __nv_bfloat16 hh0, hl0, hh1, hl1;
                    bsplit(h0, hh0, hl0); bsplit(h1, hh1, hl1);
                    __nv_bfloat162 hi; hi.x = hh0; hi.y = hh1;
                    __nv_bfloat162 lo; lo.x = hl0; lo.y = hl1;
                    *(__nv_bfloat162*)&rowp[n]      = hi;
                    *(__nv_bfloat162*)&rowp[FF + n] = lo;
                }
            }
        }
    }
}

// ------------------------- launch -------------------------------------------
extern "C" void kernel_launch(void* const* d_in, const int* in_sizes, int n_in,
                              void* d_out, int out_size) {
    const float* x   = (const float*)d_in[0];
    const float* gw1 = (const float*)d_in[1];
    const float* gb1 = (const float*)d_in[2];
    const float* gw2 = (const float*)d_in[3];
    const float* gb2 = (const float*)d_in[4];
    const float* w1  = (const float*)d_in[5];
    const float* w3  = (const float*)d_in[6];
    const float* w2  = (const float*)d_in[7];
    float* out    = (float*)d_out;
    float* logits = out + (size_t)TT * HH;

    __nv_bfloat16 *d_xs, *d_gw1s, *d_w2s, *d_hs;
    cudaGetSymbolAddress((void**)&d_xs,   g_xs);
    cudaGetSymbolAddress((void**)&d_gw1s, g_gw1s);
    cudaGetSymbolAddress((void**)&d_w2s,  g_w2s);
    cudaGetSymbolAddress((void**)&d_hs,   g_hs);
    int8_t *d_w1q, *d_w3q;
    cudaGetSymbolAddress((void**)&d_w1q, g_w1q);
    cudaGetSymbolAddress((void**)&d_w3q, g_w3q);
    float *d_act, *d_y, *d_sw1, *d_sw3;
    cudaGetSymbolAddress((void**)&d_act, g_act);
    cudaGetSymbolAddress((void**)&d_y,   g_y);
    cudaGetSymbolAddress((void**)&d_sw1, g_sw1);
    cudaGetSymbolAddress((void**)&d_sw3, g_sw3);

    const int SMEMG = 3 * 49152;    // 144KB (bf16 GEMMs, N=256)
    const int SMEMU = 3 * 32768;    // 96KB  (int8 up)
    cudaFuncSetAttribute(k_gemm<0>, cudaFuncAttributeMaxDynamicSharedMemorySize, SMEMG);
    cudaFuncSetAttribute(k_gemm<2>, cudaFuncAttributeMaxDynamicSharedMemorySize, SMEMG);
    cudaFuncSetAttribute(k_upq,     cudaFuncAttributeMaxDynamicSharedMemorySize, SMEMU);

    // fork: weight prepasses on side stream, X path on main stream
    cudaStream_t s2;
    cudaStreamCreate(&s2);
    cudaEvent_t e1, e2;
    cudaEventCreate(&e1);
    cudaEventCreate(&e2);

    k_reset_cnt<<<1, 32>>>();
    cudaEventRecord(e1, 0);
    cudaStreamWaitEvent(s2, e1, 0);
    // side chain (weights only)
    k_wmax2<<<dim3(FF / 256, 1, NE), 256, 0, s2>>>(w1, w3, d_sw1, d_sw3, HH, FF);
    k_trquant<<<dim3(FF / 32, HH / 64, NE), dim3(32, 8), 0, s2>>>(w1, d_w1q, d_sw1, HH, FF);
    k_trquant<<<dim3(FF / 32, HH / 64, NE), dim3(32, 8), 0, s2>>>(w3, d_w3q, d_sw3, HH, FF);
    k_trsplit<<<dim3(HH / 32, FF / 64, NE), dim3(32, 8), 0, s2>>>(w2, d_w2s, FF, HH);
    cudaEventRecord(e2, s2);
    // main chain (X path)
    k_splitqx<<<TT, 128>>>(x);
    k_trsplit<<<dim3(GHD / 32, HH / 64, 1), dim3(32, 8)>>>(gw1, d_gw1s, HH, GHD);
    k_gemm<0><<<dim3(GHD / 256, TT / 128, 1), 512, SMEMG>>>(d_xs, d_gw1s, HH, d_act, gb1);
    k_route<<<TT / 8, 256>>>(gw2, gb2, logits);
    k_off_k<<<1, 32>>>();
    // join, then expert GEMMs
    cudaStreamWaitEvent(0, e2, 0);
    k_upq<<<dim3(FF / 64, TT / 128, NE), 512, SMEMU>>>();
    k_gemm<2><<<dim3(HH / 256, TT / 128, NE), 512, SMEMG>>>(d_hs, d_w2s, FF, d_y, nullptr);
    k_combine<<<(TT * (HH / 4) + 255) / 256, 256>>>(out);
}